// round 17
// baseline (speedup 1.0000x reference)
#include <cuda_runtime.h>
#include <cuda_bf16.h>

#define Mdim 2048
#define Ndim 4096
#define COLS 28          // columns of A owned per block
#define NB   147         // ceil(4096/28)
#define NT   512
#define NWARP 16
#define OUTER_IT 100
#define INNER_IT 20
#define TOTAL_IT (OUTER_IT * (INNER_IT + 1))
#define RHO_C  1.0f
#define STEP_C 5e-5f
#define RPB 14           // rows owned per block (resets/epilogue): 147*14 >= 2048

// Global state (device globals: no allocation allowed)
__device__ __align__(16) float g_ybuf[3][Mdim];   // rotating Ax accumulators
__device__ __align__(16) float g_r[Mdim];         // r = s + b - u
__device__ float g_u[Mdim];
__device__ unsigned g_flags[NB];                  // barrier generation flags

__device__ __forceinline__ unsigned ldflag(const unsigned* p) {
    unsigned v;
    asm volatile("ld.global.cg.u32 %0, [%1];" : "=r"(v) : "l"(p));
    return v;
}

// Flag-array grid barrier: parallel arrival stores, warp-0-only sticky polling,
// wrap-safe generation compare, block released via __syncthreads. (Proven.)
__device__ __forceinline__ void gbar(unsigned gen) {
    __threadfence();
    __syncthreads();
    if (threadIdx.x == 0)
        asm volatile("st.global.cg.u32 [%0], %1;"
                     :: "l"(&g_flags[blockIdx.x]), "r"(gen) : "memory");
    if (threadIdx.x < 32) {
        unsigned pend = 0;
#pragma unroll
        for (int m = 0; m < 5; ++m)
            if ((int)threadIdx.x + 32 * m < NB) pend |= 1u << m;
        for (;;) {
#pragma unroll
            for (int m = 0; m < 5; ++m)
                if (pend & (1u << m)) {
                    unsigned v = ldflag(&g_flags[threadIdx.x + 32 * m]);
                    if ((int)(v - gen) >= 0) pend &= ~(1u << m);
                }
            if (__all_sync(0xffffffffu, pend == 0)) break;
        }
    }
    __syncthreads();
}

// Vector f32x4 reduction into global (sm_90+)
__device__ __forceinline__ void red4(float* p, float4 v) {
    asm volatile("red.global.add.v4.f32 [%0], {%1, %2, %3, %4};"
                 :: "l"(p), "f"(v.x), "f"(v.y), "f"(v.z), "f"(v.w) : "memory");
}

extern "C" __global__ void __launch_bounds__(NT, 1)
admm_persistent(const float* __restrict__ A,
                const float* __restrict__ b,
                const float* __restrict__ c,
                float* __restrict__ out)
{
    extern __shared__ float sm[];
    float* As  = sm;                      // COLS * Mdim floats, column-major A slice
    float* xs  = sm + COLS * Mdim;        // 32: x chunk
    float* cs  = xs + 32;                 // 32: c chunk
    float* red = cs + 32;                 // COLS * NWARP reduction scratch

    const int tid  = threadIdx.x;
    const int w    = tid >> 5;
    const int lane = tid & 31;
    const int bid  = blockIdx.x;
    const int j0   = bid * COLS;
    const int myCols = (Ndim - j0) < COLS ? (Ndim - j0) : COLS;
    const int g    = tid;                 // float4 row-group index (rows 4g..4g+3)

    // Generation base (monotonic across graph replays; all flags equal at entry)
    const unsigned base = ldflag(&g_flags[bid]);

    // ---- startup: load A column slice into SMEM (zero-padded), init state ----
    for (int idx = tid; idx < COLS * Mdim; idx += NT) {
        int i  = idx / COLS;
        int jj = idx - i * COLS;
        As[jj * Mdim + i] = (jj < myCols) ? A[(size_t)i * Ndim + (j0 + jj)] : 0.0f;
    }
    if (tid < 32) {
        xs[tid] = 0.0f;
        cs[tid] = (tid < myCols) ? c[j0 + tid] : 0.0f;
    }
    const int rb = bid * RPB;
    int nrt = Mdim - rb;
    const int nr = nrt < 0 ? 0 : (nrt < RPB ? nrt : RPB);
    for (int ii = tid; ii < nr; ii += NT) {
        int i = rb + ii;
        float bv = b[i];
        g_u[i] = 0.0f;
        g_r[i] = bv;                     // r = s + b - u = b initially
        __stcg(&g_ybuf[0][i], 0.0f);
        __stcg(&g_ybuf[1][i], 0.0f);
        __stcg(&g_ybuf[2][i], 0.0f);
    }
    gbar(base + 1u);

    const float4* As4 = (const float4*)As;   // index j*512 + g

    // Register-cached r (reloaded at each outer's first inner step)
    float4 rr = make_float4(0.f, 0.f, 0.f, 0.f);

    int bsel = 0, step = 0;
    for (int it = 0; it < TOTAL_IT; ++it) {
        // ---------------- phase A: partial Ax, RED into g_ybuf[bsel] ------------
        {
            float* yb = g_ybuf[bsel];
            float xr[COLS];
#pragma unroll
            for (int j = 0; j < COLS; ++j) xr[j] = xs[j];
            float4 a = make_float4(0.f, 0.f, 0.f, 0.f);
#pragma unroll
            for (int j = 0; j < COLS; ++j) {
                float4 v = As4[j * 512 + g];
                float xv = xr[j];
                a.x = fmaf(v.x, xv, a.x);
                a.y = fmaf(v.y, xv, a.y);
                a.z = fmaf(v.z, xv, a.z);
                a.w = fmaf(v.w, xv, a.w);
            }
            red4(&yb[4 * g], a);
        }
        gbar(base + 2u + (unsigned)it);      // the ONLY grid sync per iteration

        const float* yb = g_ybuf[bsel];
        float* zb = g_ybuf[bsel >= 1 ? bsel - 1 : 2];   // (bsel+2)%3: reset target

        if (step < INNER_IT) {
            // ------------- phase B: g = c + rho*A^T(Ax - r); x = max(x-step*g,0)
            if (step == 0)                   // r constant within an outer iteration
                rr = __ldcg((const float4*)g_r + g);
            float4 y = __ldcg((const float4*)yb + g);
            float4 e = make_float4(y.x - rr.x, y.y - rr.y, y.z - rr.z, y.w - rr.w);
            float acc[COLS];
#pragma unroll
            for (int j = 0; j < COLS; ++j) {
                float4 v = As4[j * 512 + g];
                float s = v.x * e.x;
                s = fmaf(v.y, e.y, s);
                s = fmaf(v.z, e.z, s);
                s = fmaf(v.w, e.w, s);
                acc[j] = s;
            }
#pragma unroll
            for (int j = 0; j < COLS; ++j) {
                float v = acc[j];
                v += __shfl_xor_sync(0xffffffffu, v, 16);
                v += __shfl_xor_sync(0xffffffffu, v, 8);
                v += __shfl_xor_sync(0xffffffffu, v, 4);
                v += __shfl_xor_sync(0xffffffffu, v, 2);
                v += __shfl_xor_sync(0xffffffffu, v, 1);
                if (lane == 0) red[j * NWARP + w] = v;
            }
            // reset the buffer accumulated 2 iterations from now (safe: post-barrier)
            for (int ii = tid; ii < nr; ii += NT) __stcg(&zb[rb + ii], 0.0f);
            __syncthreads();
            if (tid < COLS) {
                float gsum = 0.0f;
#pragma unroll
                for (int k = 0; k < NWARP; ++k) gsum += red[tid * NWARP + k];
                float xn = xs[tid] - STEP_C * (cs[tid] + RHO_C * gsum);
                xs[tid] = fmaxf(xn, 0.0f);
            }
            __syncthreads();
            ++step;
        } else {
            // ------------- epilogue: s, u, r updates (row-owned) ---------------
            for (int ii = tid; ii < nr; ii += NT) {
                int i = rb + ii;
                float Ax = __ldcg(&yb[i]);
                float bi = b[i];
                float ui = g_u[i];
                float sn = fmaxf(Ax - bi + ui, 0.0f);
                float un = ui + (Ax - sn - bi);
                g_u[i] = un;
                g_r[i] = sn + bi - un;           // r = s + b - u
                __stcg(&zb[i], 0.0f);
                if (it == TOTAL_IT - 1) {
                    out[Ndim + i]            = sn;          // s
                    out[Ndim + Mdim + i]     = un;          // u
                    out[Ndim + 2 * Mdim + i] = -RHO_C * un; // lambda_kkt
                }
            }
            step = 0;
        }
        bsel = (bsel + 1 == 3) ? 0 : bsel + 1;
    }

    // final x (block-local)
    if (tid < myCols) out[j0 + tid] = xs[tid];
}

extern "C" void kernel_launch(void* const* d_in, const int* in_sizes, int n_in,
                              void* d_out, int out_size) {
    const float* A = nullptr;
    const float* b = nullptr;
    const float* c = nullptr;
    for (int k = 0; k < n_in; ++k) {
        if (in_sizes[k] == Mdim * Ndim)      A = (const float*)d_in[k];
        else if (in_sizes[k] == Mdim)        b = (const float*)d_in[k];
        else if (in_sizes[k] == Ndim)        c = (const float*)d_in[k];
    }
    float* out = (float*)d_out;
    size_t shmem = (size_t)(COLS * Mdim + 32 + 32 + COLS * NWARP) * sizeof(float); // 231,424 B
    cudaFuncSetAttribute(admm_persistent,
                         cudaFuncAttributeMaxDynamicSharedMemorySize, (int)shmem);
    admm_persistent<<<NB, NT, shmem>>>(A, b, c, out);
}